// round 6
// baseline (speedup 1.0000x reference)
#include <cuda_runtime.h>
#include <cstdint>

#define C_INN 128
#define C_OUTT 64
#define BB 8
#define NN 2048
#define LOG2E 1.4426950408889634f

// ---------------------------------------------------------------------------
// Scratch (__device__ globals: allocation-free per harness rules)
// ---------------------------------------------------------------------------
__device__ float  g_Wh[BB * NN * C_OUTT];       // tf32-rounded Wh, 4 MB
__device__ float2 g_E1i[BB * NN];               // {exp(f1), exp(0.2 f1)}
__device__ float2 g_E2i[BB * NN];               // {exp(f2), exp(0.2 f2)}
__device__ unsigned g_Mt[(NN / 32) * NN];       // transposed bitmask [word][i]

__device__ __forceinline__ float fast_exp(float x) {
    float r;
    asm("ex2.approx.f32 %0, %1;" : "=f"(r) : "f"(x * LOG2E));
    return r;
}

__device__ __forceinline__ uint32_t cvt_tf32(float f) {
    uint32_t u;
    asm("cvt.rna.tf32.f32 %0, %1;" : "=r"(u) : "f"(f));
    return u;
}

__device__ __forceinline__ uint32_t smem_addr(const void* p) {
    return (uint32_t)__cvta_generic_to_shared(p);
}

__device__ __forceinline__ void cpa16(uint32_t d, const void* s) {
    asm volatile("cp.async.cg.shared.global [%0], [%1], 16;" :: "r"(d), "l"(s));
}
__device__ __forceinline__ void cpa8(uint32_t d, const void* s) {
    asm volatile("cp.async.ca.shared.global [%0], [%1], 8;" :: "r"(d), "l"(s));
}
__device__ __forceinline__ void cpa4(uint32_t d, const void* s) {
    asm volatile("cp.async.ca.shared.global [%0], [%1], 4;" :: "r"(d), "l"(s));
}
__device__ __forceinline__ void cpa_wait_all() {
    asm volatile("cp.async.commit_group;\n\tcp.async.wait_group 0;" ::: "memory");
}

// ---------------------------------------------------------------------------
// Kernel 1: Wh = x @ W, SMEM-staged. 512 thr = 16 warps x 4 rows = 64 rows
// per CTA, grid 256 (higher occupancy than R5's 256-thr version).
// W interleaved float2{W[c][n], W[c][n+32]} -> LDS.64.
// Fused epilogue: f1/f2 reduction + exp tables; Wh stored tf32-rounded.
// ---------------------------------------------------------------------------
__global__ void __launch_bounds__(512) k_wh(const float* __restrict__ x,
                                            const float* __restrict__ W,
                                            const float* __restrict__ attn)
{
    extern __shared__ float sm[];
    float* Wsh = sm;          // 8192 floats
    float* xsh = sm + 8192;   // 8192 floats: [64][128]

    int t = threadIdx.x, warp = t >> 5, lane = t & 31;
    int base = blockIdx.x * 64;

    #pragma unroll
    for (int k = 0; k < 16; k++) {
        int idx = t + k * 512;
        int c = idx >> 6, n = idx & 63;
        Wsh[(c * 32 + (n & 31)) * 2 + (n >> 5)] = W[idx];
    }
    {
        const float4* xr = (const float4*)(x + (size_t)base * C_INN);
        float4* xd = (float4*)xsh;
        #pragma unroll
        for (int k = 0; k < 4; k++) xd[t + k * 512] = xr[t + k * 512];
    }
    __syncthreads();

    int r = warp * 4;
    float a0[4], a1[4];
    #pragma unroll
    for (int q = 0; q < 4; q++) { a0[q] = 0.f; a1[q] = 0.f; }

    #pragma unroll 4
    for (int c4 = 0; c4 < C_INN; c4 += 4) {
        float2 w0 = *(float2*)&Wsh[((c4 + 0) * 32 + lane) * 2];
        float2 w1 = *(float2*)&Wsh[((c4 + 1) * 32 + lane) * 2];
        float2 w2 = *(float2*)&Wsh[((c4 + 2) * 32 + lane) * 2];
        float2 w3 = *(float2*)&Wsh[((c4 + 3) * 32 + lane) * 2];
        #pragma unroll
        for (int q = 0; q < 4; q++) {
            float4 xv = *(const float4*)&xsh[(r + q) * C_INN + c4];
            a0[q] = fmaf(xv.x, w0.x, a0[q]); a1[q] = fmaf(xv.x, w0.y, a1[q]);
            a0[q] = fmaf(xv.y, w1.x, a0[q]); a1[q] = fmaf(xv.y, w1.y, a1[q]);
            a0[q] = fmaf(xv.z, w2.x, a0[q]); a1[q] = fmaf(xv.z, w2.y, a1[q]);
            a0[q] = fmaf(xv.w, w3.x, a0[q]); a1[q] = fmaf(xv.w, w3.y, a1[q]);
        }
    }

    float at1a = attn[lane], at1b = attn[32 + lane];
    float at2a = attn[64 + lane], at2b = attn[96 + lane];

    #pragma unroll
    for (int q = 0; q < 4; q++) {
        int row = base + r + q;
        float p1 = a0[q] * at1a + a1[q] * at1b;
        float p2 = a0[q] * at2a + a1[q] * at2b;
        #pragma unroll
        for (int s = 16; s; s >>= 1) {
            p1 += __shfl_xor_sync(0xffffffffu, p1, s);
            p2 += __shfl_xor_sync(0xffffffffu, p2, s);
        }
        if (lane == 0) {
            g_E1i[row] = make_float2(fast_exp(p1), fast_exp(0.2f * p1));
            g_E2i[row] = make_float2(fast_exp(p2), fast_exp(0.2f * p2));
        }
        g_Wh[(size_t)row * C_OUTT + lane]      = __uint_as_float(cvt_tf32(a0[q]));
        g_Wh[(size_t)row * C_OUTT + 32 + lane] = __uint_as_float(cvt_tf32(a1[q]));
    }
}

// ---------------------------------------------------------------------------
// Kernel 2: bit-pack mask, stored TRANSPOSED: g_Mt[word][i].
// ---------------------------------------------------------------------------
__global__ void __launch_bounds__(256) k_mask(const int* __restrict__ A)
{
    __shared__ unsigned char nib[256];
    int t = threadIdx.x;
    int i = blockIdx.x >> 1;
    int wb = (blockIdx.x & 1) * 32;
    int4 v = ((const int4*)A)[(size_t)blockIdx.x * 256 + t];
    unsigned n = (v.x > 0 ? 1u : 0u) | (v.y > 0 ? 2u : 0u) |
                 (v.z > 0 ? 4u : 0u) | (v.w > 0 ? 8u : 0u);
    nib[t] = (unsigned char)n;
    __syncthreads();
    if (t < 32) {
        const unsigned char* p = nib + t * 8;
        unsigned w = 0;
        #pragma unroll
        for (int s = 0; s < 8; s++) w |= ((unsigned)(p[s] & 0xFu)) << (4 * s);
        g_Mt[(size_t)(wb + t) * NN + i] = w;
    }
}

// ---------------------------------------------------------------------------
// Kernel 3: fused P-build + mma.sync tf32 aggregation, K-split warp pairs.
// 256 thr = 8 warps = 4 warpM x 2 kwarp; 64 i-rows/CTA; grid 256.
// cp.async staging (no prefetch registers) -> <=64 regs -> 4 CTAs/SM.
// Warp tile: M=16, N=64, half the k-steps of each 128-j tile.
// ---------------------------------------------------------------------------
__global__ void __launch_bounds__(256, 4) k_gat(float* __restrict__ out)
{
    __shared__ float    Whs[128 * 72];   // 36864 B; reused as reduction buffer
    __shared__ float2   E2s[128];
    __shared__ unsigned Msh[4][64];

    int t = threadIdx.x;
    int lane = t & 31, w = t >> 5;
    int warpM = w >> 1, kwarp = w & 1;
    int g = lane >> 2, tk = lane & 3;
    int b = blockIdx.x >> 5, i0 = (blockIdx.x & 31) << 6;
    int b2048 = b * NN;

    int r0 = warpM * 16 + g, r1 = r0 + 8;
    float2 e1a = g_E1i[b2048 + i0 + r0];
    float2 e1b = g_E1i[b2048 + i0 + r1];

    float c[8][4];
    #pragma unroll
    for (int nt = 0; nt < 8; nt++)
        #pragma unroll
        for (int k = 0; k < 4; k++) c[nt][k] = 0.f;
    float z0 = 0.f, z1 = 0.f;

    unsigned mt0 = 1u << tk;
    unsigned mt1 = 16u << tk;

    const float4* wh4 = (const float4*)(g_Wh + (size_t)b2048 * C_OUTT);
    uint32_t whs_a = smem_addr(Whs);
    uint32_t msh_a = smem_addr(&Msh[0][0]);
    uint32_t e2s_a = smem_addr(E2s);

    for (int jt = 0; jt < 16; jt++) {
        __syncthreads();                   // previous tile's compute done
        // stage Wh tile via cp.async: 2048 float4 over 256 threads
        {
            const float4* src = wh4 + jt * 2048;
            #pragma unroll
            for (int k = 0; k < 8; k++) {
                int idx = t + k * 256;
                uint32_t d = whs_a + (uint32_t)((idx >> 4) * 72 + ((idx & 15) << 2)) * 4u;
                cpa16(d, src + idx);
            }
        }
        // mask words: 4 x 64 = 256, one per thread
        cpa4(msh_a + (uint32_t)t * 4u,
             &g_Mt[(size_t)(jt * 4 + (t >> 6)) * NN + i0 + (t & 63)]);
        // E2 pairs: 128 float2
        if (t < 128) cpa8(e2s_a + (uint32_t)t * 8u, &g_E2i[b2048 + jt * 128 + t]);
        cpa_wait_all();
        __syncthreads();

        // this warp's 8 k-steps (kwarp selects which half of the j-tile)
        unsigned mw0 = 0, mw1 = 0;
        #pragma unroll
        for (int ks = 0; ks < 8; ks++) {
            int ksg = kwarp * 8 + ks;
            if ((ks & 3) == 0) {
                mw0 = Msh[kwarp * 2 + (ks >> 2)][r0];
                mw1 = Msh[kwarp * 2 + (ks >> 2)][r1];
            }
            int j0 = ksg * 8;
            float2 ea = E2s[j0 + tk];
            float2 eb = E2s[j0 + tk + 4];
            unsigned s0 = mt0 << ((ks & 3) * 8);
            unsigned s1 = mt1 << ((ks & 3) * 8);

            float m;
            m = fmaxf(e1a.x * ea.x, e1a.y * ea.y);
            float a0 = (mw0 & s0) ? m : 0.f;
            m = fmaxf(e1b.x * ea.x, e1b.y * ea.y);
            float a1 = (mw1 & s0) ? m : 0.f;
            m = fmaxf(e1a.x * eb.x, e1a.y * eb.y);
            float a2 = (mw0 & s1) ? m : 0.f;
            m = fmaxf(e1b.x * eb.x, e1b.y * eb.y);
            float a3 = (mw1 & s1) ? m : 0.f;

            z0 += a0 + a2;
            z1 += a1 + a3;

            uint32_t ua0 = __float_as_uint(a0), ua1 = __float_as_uint(a1);
            uint32_t ua2 = __float_as_uint(a2), ua3 = __float_as_uint(a3);

            const float* brow = Whs + (j0 + tk) * 72 + g;
            #pragma unroll
            for (int nt = 0; nt < 8; nt++) {
                uint32_t ub0 = __float_as_uint(brow[nt * 8]);
                uint32_t ub1 = __float_as_uint(brow[288 + nt * 8]);
                asm volatile(
                    "mma.sync.aligned.m16n8k8.row.col.f32.tf32.tf32.f32 "
                    "{%0,%1,%2,%3}, {%4,%5,%6,%7}, {%8,%9}, {%0,%1,%2,%3};"
                    : "+f"(c[nt][0]), "+f"(c[nt][1]), "+f"(c[nt][2]), "+f"(c[nt][3])
                    : "r"(ua0), "r"(ua1), "r"(ua2), "r"(ua3), "r"(ub0), "r"(ub1));
            }
        }
    }

    // intra-warp Z reduce over the 4 tk lanes
    z0 += __shfl_xor_sync(0xffffffffu, z0, 1);
    z0 += __shfl_xor_sync(0xffffffffu, z0, 2);
    z1 += __shfl_xor_sync(0xffffffffu, z1, 1);
    z1 += __shfl_xor_sync(0xffffffffu, z1, 2);

    // cross-kwarp reduction through reused Whs
    __syncthreads();
    float4* red4 = (float4*)Whs;                       // [warpM][nt][lane]
    float2* zred = (float2*)((char*)Whs + 16384);

    if (kwarp == 1) {
        #pragma unroll
        for (int nt = 0; nt < 8; nt++)
            red4[(warpM * 8 + nt) * 32 + lane] =
                make_float4(c[nt][0], c[nt][1], c[nt][2], c[nt][3]);
        zred[warpM * 32 + lane] = make_float2(z0, z1);
    }
    __syncthreads();

    if (kwarp == 0) {
        float2 zz = zred[warpM * 32 + lane];
        float inv0 = 1.f / (z0 + zz.x);
        float inv1 = 1.f / (z1 + zz.y);

        float* o0 = out + (size_t)(b2048 + i0 + r0) * C_OUTT + tk * 2;
        float* o1 = out + (size_t)(b2048 + i0 + r1) * C_OUTT + tk * 2;
        #pragma unroll
        for (int nt = 0; nt < 8; nt++) {
            float4 v = red4[(warpM * 8 + nt) * 32 + lane];
            *(float2*)(o0 + nt * 8) =
                make_float2((c[nt][0] + v.x) * inv0, (c[nt][1] + v.y) * inv0);
            *(float2*)(o1 + nt * 8) =
                make_float2((c[nt][2] + v.z) * inv1, (c[nt][3] + v.w) * inv1);
        }
    }
}

// ---------------------------------------------------------------------------
extern "C" void kernel_launch(void* const* d_in, const int* in_sizes, int n_in,
                              void* d_out, int out_size)
{
    const float* x    = (const float*)d_in[0];   // (8,2048,128) f32
    const int*   A    = (const int*)d_in[1];     // (2048,2048) i32
    const float* W    = (const float*)d_in[2];   // (128,64) f32
    const float* attn = (const float*)d_in[3];   // (128,1) f32
    float* out = (float*)d_out;                  // (8,2048,64) f32

    cudaFuncSetAttribute(k_wh, cudaFuncAttributeMaxDynamicSharedMemorySize, 65536);

    k_wh  <<<BB * NN / 64, 512, 65536>>>(x, W, attn);
    k_mask<<<NN * NN / 1024, 256>>>(A);
    k_gat <<<BB * (NN / 64), 256>>>(out);
}

// round 8
// speedup vs baseline: 1.2290x; 1.2290x over previous
#include <cuda_runtime.h>
#include <cstdint>

#define C_INN 128
#define C_OUTT 64
#define BB 8
#define NN 2048
#define LOG2E 1.4426950408889634f

// ---------------------------------------------------------------------------
// Scratch (__device__ globals: allocation-free per harness rules)
// ---------------------------------------------------------------------------
__device__ float  g_Wh[BB * NN * C_OUTT];       // tf32-rounded Wh, 4 MB
__device__ float2 g_E1i[BB * NN];               // {exp(f1), exp(0.2 f1)}
__device__ float2 g_E2i[BB * NN];               // {exp(f2), exp(0.2 f2)}
__device__ unsigned g_Mt[(NN / 32) * NN];       // transposed bitmask [word][i]

__device__ __forceinline__ float fast_exp(float x) {
    float r;
    asm("ex2.approx.f32 %0, %1;" : "=f"(r) : "f"(x * LOG2E));
    return r;
}

__device__ __forceinline__ uint32_t cvt_tf32(float f) {
    uint32_t u;
    asm("cvt.rna.tf32.f32 %0, %1;" : "=r"(u) : "f"(f));
    return u;
}
__device__ __forceinline__ float tf32f(float f) {
    return __uint_as_float(cvt_tf32(f));
}

// ---------------------------------------------------------------------------
// Kernel 1: Wh = x @ W via tf32 mma.sync; f1/f2 via fp32 x@(W@a) factorization.
// CTA: 256 thr = 8 warps (4 warpM x 2 warpN); 64 rows; grid 256.
// x staged tf32-rounded at stride 132 (conflict-free A-fragment LDS);
// W staged tf32-rounded at stride 72 (proven k_gat B layout).
// Epilogue: w12 = W@[a1,a2] per-CTA, fp32 f-pass, exp tables, Wh store.
// ---------------------------------------------------------------------------
__global__ void __launch_bounds__(256) k_wh(const float* __restrict__ x,
                                            const float* __restrict__ W,
                                            const float* __restrict__ attn)
{
    extern __shared__ float sm[];
    float*  xs  = sm;                       // 64 x 132
    float*  Ws  = sm + 64 * 132;            // 128 x 72
    float2* w12 = (float2*)(Ws + 128 * 72); // 128 x {w1,w2}

    int t = threadIdx.x, wid = t >> 5, lane = t & 31;
    int g = lane >> 2, tk = lane & 3;
    int warpM = wid >> 1, warpN = wid & 1;
    int base = blockIdx.x * 64;

    // stage x (tf32-rounded): 2048 float4 over 256 threads
    {
        const float4* xr = (const float4*)(x + (size_t)base * C_INN);
        #pragma unroll
        for (int k = 0; k < 8; k++) {
            int i4 = t + k * 256;
            float4 v = xr[i4];
            int row = i4 >> 5, c = (i4 & 31) << 2;
            *(float4*)&xs[row * 132 + c] =
                make_float4(tf32f(v.x), tf32f(v.y), tf32f(v.z), tf32f(v.w));
        }
    }
    // stage W (tf32-rounded): 2048 float4 over 256 threads, stride 72
    {
        const float4* wr = (const float4*)W;
        #pragma unroll
        for (int k = 0; k < 8; k++) {
            int i4 = t + k * 256;
            float4 v = wr[i4];
            int c = i4 >> 4, n = (i4 & 15) << 2;
            *(float4*)&Ws[c * 72 + n] =
                make_float4(tf32f(v.x), tf32f(v.y), tf32f(v.z), tf32f(v.w));
        }
    }
    __syncthreads();

    // per-CTA w1 = W@a1, w2 = W@a2 (tiny, redundant across CTAs)
    if (t < 128) {
        float w1 = 0.f, w2 = 0.f;
        const float* wrow = Ws + t * 72;
        #pragma unroll 8
        for (int n = 0; n < 64; n++) {
            float wv = wrow[n];
            w1 = fmaf(wv, attn[n], w1);
            w2 = fmaf(wv, attn[64 + n], w2);
        }
        w12[t] = make_float2(w1, w2);
    }
    __syncthreads();

    // MMA: warp tile M=16 (r0..r0+15), N=32 (warpN half), K=128
    int r0 = warpM * 16;
    float acc[4][4];
    #pragma unroll
    for (int nt = 0; nt < 4; nt++)
        #pragma unroll
        for (int k = 0; k < 4; k++) acc[nt][k] = 0.f;

    #pragma unroll
    for (int ks = 0; ks < 16; ks++) {
        int c0 = ks * 8;
        uint32_t a0 = __float_as_uint(xs[(r0 + g) * 132 + c0 + tk]);
        uint32_t a1 = __float_as_uint(xs[(r0 + g + 8) * 132 + c0 + tk]);
        uint32_t a2 = __float_as_uint(xs[(r0 + g) * 132 + c0 + tk + 4]);
        uint32_t a3 = __float_as_uint(xs[(r0 + g + 8) * 132 + c0 + tk + 4]);
        const float* brow = Ws + (c0 + tk) * 72 + warpN * 32 + g;
        #pragma unroll
        for (int nt = 0; nt < 4; nt++) {
            uint32_t ub0 = __float_as_uint(brow[nt * 8]);
            uint32_t ub1 = __float_as_uint(brow[288 + nt * 8]);
            asm volatile(
                "mma.sync.aligned.m16n8k8.row.col.f32.tf32.tf32.f32 "
                "{%0,%1,%2,%3}, {%4,%5,%6,%7}, {%8,%9}, {%0,%1,%2,%3};"
                : "+f"(acc[nt][0]), "+f"(acc[nt][1]), "+f"(acc[nt][2]), "+f"(acc[nt][3])
                : "r"(a0), "r"(a1), "r"(a2), "r"(a3), "r"(ub0), "r"(ub1));
        }
    }

    // f-pass: 4 threads per row, 32 c's each, fp32
    {
        int row = t >> 2, q = t & 3;
        const float4* xv4 = (const float4*)&xs[row * 132 + q * 32];
        const float4* wv4 = (const float4*)(w12 + q * 32);
        float f1 = 0.f, f2 = 0.f;
        #pragma unroll
        for (int k = 0; k < 8; k++) {
            float4 xv = xv4[k];
            float4 wa = wv4[2 * k], wb = wv4[2 * k + 1];
            f1 += xv.x * wa.x + xv.y * wa.z + xv.z * wb.x + xv.w * wb.z;
            f2 += xv.x * wa.y + xv.y * wa.w + xv.z * wb.y + xv.w * wb.w;
        }
        f1 += __shfl_xor_sync(0xffffffffu, f1, 1);
        f1 += __shfl_xor_sync(0xffffffffu, f1, 2);
        f2 += __shfl_xor_sync(0xffffffffu, f2, 1);
        f2 += __shfl_xor_sync(0xffffffffu, f2, 2);
        if (q == 0) {
            int gr = base + row;
            g_E1i[gr] = make_float2(fast_exp(f1), fast_exp(0.2f * f1));
            g_E2i[gr] = make_float2(fast_exp(f2), fast_exp(0.2f * f2));
        }
    }

    // store Wh (tf32-rounded for k_gat's B operand)
    #pragma unroll
    for (int nt = 0; nt < 4; nt++) {
        int n = warpN * 32 + nt * 8 + tk * 2;
        *(float2*)&g_Wh[(size_t)(base + r0 + g) * C_OUTT + n] =
            make_float2(tf32f(acc[nt][0]), tf32f(acc[nt][1]));
        *(float2*)&g_Wh[(size_t)(base + r0 + g + 8) * C_OUTT + n] =
            make_float2(tf32f(acc[nt][2]), tf32f(acc[nt][3]));
    }
}

// ---------------------------------------------------------------------------
// Kernel 2: bit-pack mask, stored TRANSPOSED: g_Mt[word][i].
// ---------------------------------------------------------------------------
__global__ void __launch_bounds__(256) k_mask(const int* __restrict__ A)
{
    __shared__ unsigned char nib[256];
    int t = threadIdx.x;
    int i = blockIdx.x >> 1;
    int wb = (blockIdx.x & 1) * 32;
    int4 v = ((const int4*)A)[(size_t)blockIdx.x * 256 + t];
    unsigned n = (v.x > 0 ? 1u : 0u) | (v.y > 0 ? 2u : 0u) |
                 (v.z > 0 ? 4u : 0u) | (v.w > 0 ? 8u : 0u);
    nib[t] = (unsigned char)n;
    __syncthreads();
    if (t < 32) {
        const unsigned char* p = nib + t * 8;
        unsigned w = 0;
        #pragma unroll
        for (int s = 0; s < 8; s++) w |= ((unsigned)(p[s] & 0xFu)) << (4 * s);
        g_Mt[(size_t)(wb + t) * NN + i] = w;
    }
}

// ---------------------------------------------------------------------------
// Kernel 3: fused P-build + mma.sync tf32 aggregation, K-split warp pairs.
// (R5 verbatim — proven 55.3us-era configuration.)
// ---------------------------------------------------------------------------
__global__ void __launch_bounds__(512, 1) k_gat(float* __restrict__ out)
{
    __shared__ float    Whs[128 * 72];   // 36864 B; reused as reduction buffer
    __shared__ float2   E2s[128];
    __shared__ unsigned Msh[4][128];

    int t = threadIdx.x;
    int lane = t & 31, w = t >> 5;
    int warpM = w >> 1, kwarp = w & 1;
    int g = lane >> 2, tk = lane & 3;
    int b = blockIdx.x >> 4, i0 = (blockIdx.x & 15) << 7;
    int b2048 = b * NN;

    int r0 = warpM * 16 + g, r1 = r0 + 8;
    float2 e1a = g_E1i[b2048 + i0 + r0];
    float2 e1b = g_E1i[b2048 + i0 + r1];

    float c[8][4];
    #pragma unroll
    for (int nt = 0; nt < 8; nt++)
        #pragma unroll
        for (int k = 0; k < 4; k++) c[nt][k] = 0.f;
    float z0 = 0.f, z1 = 0.f;

    unsigned mt0 = 1u << tk;
    unsigned mt1 = 16u << tk;

    const float4* wh4 = (const float4*)(g_Wh + (size_t)b2048 * C_OUTT);

    // register prefetch buffers
    float4 pw[4]; unsigned pm; float2 pe;
    {
        #pragma unroll
        for (int k = 0; k < 4; k++) pw[k] = wh4[t + k * 512];
        pm = g_Mt[(size_t)(t >> 7) * NN + i0 + (t & 127)];
        if (t < 128) pe = g_E2i[b2048 + t];
    }

    for (int jt = 0; jt < 16; jt++) {
        __syncthreads();                       // previous compute done
        #pragma unroll
        for (int k = 0; k < 4; k++) {
            int idx = t + k * 512;
            *(float4*)&Whs[(idx >> 4) * 72 + ((idx & 15) << 2)] = pw[k];
        }
        Msh[t >> 7][t & 127] = pm;
        if (t < 128) E2s[t] = pe;
        __syncthreads();

        // prefetch next tile (wrap at 15 -> harmless re-read of tile 0)
        {
            int jn = (jt + 1) & 15;
            #pragma unroll
            for (int k = 0; k < 4; k++) pw[k] = wh4[jn * 2048 + t + k * 512];
            pm = g_Mt[(size_t)(jn * 4 + (t >> 7)) * NN + i0 + (t & 127)];
            if (t < 128) pe = g_E2i[b2048 + jn * 128 + t];
        }

        // this warp's 8 k-steps (kwarp selects which half of the j-tile)
        unsigned mw0 = 0, mw1 = 0;
        #pragma unroll
        for (int ks = 0; ks < 8; ks++) {
            int ksg = kwarp * 8 + ks;
            if ((ks & 3) == 0) {
                mw0 = Msh[kwarp * 2 + (ks >> 2)][r0];
                mw1 = Msh[kwarp * 2 + (ks >> 2)][r1];
            }
            int j0 = ksg * 8;
            float2 ea = E2s[j0 + tk];
            float2 eb = E2s[j0 + tk + 4];
            unsigned s0 = mt0 << ((ks & 3) * 8);
            unsigned s1 = mt1 << ((ks & 3) * 8);

            float m;
            m = fmaxf(e1a.x * ea.x, e1a.y * ea.y);
            float a0 = (mw0 & s0) ? m : 0.f;
            m = fmaxf(e1b.x * ea.x, e1b.y * ea.y);
            float a1 = (mw1 & s0) ? m : 0.f;
            m = fmaxf(e1a.x * eb.x, e1a.y * eb.y);
            float a2 = (mw0 & s1) ? m : 0.f;
            m = fmaxf(e1b.x * eb.x, e1b.y * eb.y);
            float a3 = (mw1 & s1) ? m : 0.f;

            z0 += a0 + a2;
            z1 += a1 + a3;

            uint32_t ua0 = __float_as_uint(a0), ua1 = __float_as_uint(a1);
            uint32_t ua2 = __float_as_uint(a2), ua3 = __float_as_uint(a3);

            const float* brow = Whs + (j0 + tk) * 72 + g;
            #pragma unroll
            for (int nt = 0; nt < 8; nt++) {
                uint32_t ub0 = __float_as_uint(brow[nt * 8]);
                uint32_t ub1 = __float_as_uint(brow[288 + nt * 8]);
                asm volatile(
                    "mma.sync.aligned.m16n8k8.row.col.f32.tf32.tf32.f32 "
                    "{%0,%1,%2,%3}, {%4,%5,%6,%7}, {%8,%9}, {%0,%1,%2,%3};"
                    : "+f"(c[nt][0]), "+f"(c[nt][1]), "+f"(c[nt][2]), "+f"(c[nt][3])
                    : "r"(ua0), "r"(ua1), "r"(ua2), "r"(ua3), "r"(ub0), "r"(ub1));
            }
        }
    }

    // intra-warp Z reduce over the 4 tk lanes
    z0 += __shfl_xor_sync(0xffffffffu, z0, 1);
    z0 += __shfl_xor_sync(0xffffffffu, z0, 2);
    z1 += __shfl_xor_sync(0xffffffffu, z1, 1);
    z1 += __shfl_xor_sync(0xffffffffu, z1, 2);

    // cross-kwarp reduction through reused Whs
    __syncthreads();
    float4* red4 = (float4*)Whs;                       // [warpM][nt][lane]
    float2* zred = (float2*)((char*)Whs + 32768);

    if (kwarp == 1) {
        #pragma unroll
        for (int nt = 0; nt < 8; nt++)
            red4[(warpM * 8 + nt) * 32 + lane] =
                make_float4(c[nt][0], c[nt][1], c[nt][2], c[nt][3]);
        zred[warpM * 32 + lane] = make_float2(z0, z1);
    }
    __syncthreads();

    if (kwarp == 0) {
        float2 zz = zred[warpM * 32 + lane];
        float inv0 = 1.f / (z0 + zz.x);
        float inv1 = 1.f / (z1 + zz.y);

        float* o0 = out + (size_t)(b2048 + i0 + r0) * C_OUTT + tk * 2;
        float* o1 = out + (size_t)(b2048 + i0 + r1) * C_OUTT + tk * 2;
        #pragma unroll
        for (int nt = 0; nt < 8; nt++) {
            float4 v = red4[(warpM * 8 + nt) * 32 + lane];
            *(float2*)(o0 + nt * 8) =
                make_float2((c[nt][0] + v.x) * inv0, (c[nt][1] + v.y) * inv0);
            *(float2*)(o1 + nt * 8) =
                make_float2((c[nt][2] + v.z) * inv1, (c[nt][3] + v.w) * inv1);
        }
    }
}

// ---------------------------------------------------------------------------
extern "C" void kernel_launch(void* const* d_in, const int* in_sizes, int n_in,
                              void* d_out, int out_size)
{
    const float* x    = (const float*)d_in[0];   // (8,2048,128) f32
    const int*   A    = (const int*)d_in[1];     // (2048,2048) i32
    const float* W    = (const float*)d_in[2];   // (128,64) f32
    const float* attn = (const float*)d_in[3];   // (128,1) f32
    float* out = (float*)d_out;                  // (8,2048,64) f32

    const int wh_smem = (64 * 132 + 128 * 72 + 256) * 4;   // 71680 B
    cudaFuncSetAttribute(k_wh, cudaFuncAttributeMaxDynamicSharedMemorySize, wh_smem);

    k_wh  <<<BB * NN / 64, 256, wh_smem>>>(x, W, attn);
    k_mask<<<NN * NN / 1024, 256>>>(A);
    k_gat <<<BB * (NN / 128), 512>>>(out);
}